// round 13
// baseline (speedup 1.0000x reference)
#include <cuda_runtime.h>

#define N_NODES 4096
#define NUM_REL 200
#define D 32
#define E_EDGES 16384
#define B_ROWS 2048
#define CAP 64
#define FULL 0xffffffffu
#define GRID_BLOCKS 148
#define BLOCK_THREADS 1024
#define EPB 111    // edges per block      (148*111 = 16428 >= 16384)
#define RPB 14     // rows per block       (148*14  = 2072  >= 2048)
#define CZPB 56    // counter zeros/block  (148*56  = 8288  >= 8192)
#define GPB 271    // gram entries/block   (148*271 = 40108 >= 40000)
#define YPB 260    // Y entries/block      (148*260 = 38480 >= 38400)
#define CPB 886    // copy float4s/block   (148*886 = 131128 >= 131072)

// ---------------- persistent scratch (no allocation) ----------------
__device__ int      g_cnt[2][2 * N_NODES];       // ping-pong by epoch parity
__device__ int      g_list[2 * N_NODES * CAP];   // packed (other<<8)|type
__device__ float    g_Y[6 * 256 * 32];           // padded type dim: any ty<=255 in-bounds
__device__ float    g_R[NUM_REL * 256];          // padded rows: any ty<=255 in-bounds
__device__ unsigned g_arrive[GRID_BLOCKS];       // per-block arrival flags
__device__ unsigned g_epoch = 0;

__device__ __forceinline__ unsigned ld_acq(const unsigned* p) {
    unsigned v;
    asm volatile("ld.acquire.gpu.u32 %0, [%1];" : "=r"(v) : "l"(p) : "memory");
    return v;
}
__device__ __forceinline__ void st_rel(unsigned* p, unsigned v) {
    asm volatile("st.release.gpu.u32 [%0], %1;" :: "l"(p), "r"(v) : "memory");
}

__global__ void __launch_bounds__(BLOCK_THREADS, 1)
k_fused(const int* __restrict__ edge_src, const int* __restrict__ edge_dst,
        const int* __restrict__ edge_type, const int* __restrict__ nbr,
        const int* __restrict__ n2r, const float* __restrict__ rel_emb,
        const float* __restrict__ W1, const float* __restrict__ b1,
        float* __restrict__ out) {
    extern __shared__ float smem[];
    float* srel  = smem;                   // [200*33] padded
    float* sWT   = smem + 6600;            // [6*1056] sWT[i*1056+k*33+d]=W1[i][d][k]
    float* sB    = smem + 12936;           // [192]
    float* s_agg = smem + 13128;           // [16*32]
    int4*  sMeta = (int4*)(smem + 13640);  // [16] (u, v, relb|te<<8, eb)
    __shared__ unsigned s_ep;

    const int tid = threadIdx.x, bid = blockIdx.x;

    // epoch: ONE acquire load per block, broadcast through smem
    if (tid == 0) s_ep = ld_acq(&g_epoch);

    // ---- vectorized smem staging (independent of epoch) ----
    for (int idx = tid; idx < 1600; idx += BLOCK_THREADS) {   // rel_emb: 1600 float4
        float4 v = __ldg(&((const float4*)rel_emb)[idx]);
        int base = idx << 2, t = base >> 5, rem = base & 31;
        float* dst = &srel[t * 33 + rem];
        dst[0] = v.x; dst[1] = v.y; dst[2] = v.z; dst[3] = v.w;
    }
    for (int idx = tid; idx < 1536; idx += BLOCK_THREADS) {   // W1: 1536 float4
        float4 v = __ldg(&((const float4*)W1)[idx]);
        int base = idx << 2;
        int i = base >> 10, r = base & 1023, d = r >> 5, k0 = r & 31;
        float* dst = &sWT[i * 1056 + k0 * 33 + d];            // stride 33 per k
        dst[0] = v.x; dst[33] = v.y; dst[66] = v.z; dst[99] = v.w;
    }
    if (tid >= 832 && tid < 832 + 192) sB[tid - 832] = __ldg(&b1[tid - 832]);
    __syncthreads();                         // publishes s_ep AND srel/sWT

    const unsigned ep0 = s_ep;
    int* cntA = g_cnt[ep0 & 1];
    int* cntZ = g_cnt[(ep0 & 1) ^ 1];

    // ---- balanced phase A (contiguous per-block slices, all 148 SMs) ----
    if (tid >= 256 && tid < 256 + 16) {               // this block's rows (pad to 16)
        int r = tid - 256;
        int b = bid * RPB + r;
        if (r < RPB && b < B_ROWS) {
            int eb = __ldg(&nbr[b]);
            int te = __ldg(&edge_type[eb]);
            sMeta[r] = make_int4(__ldg(&edge_src[eb]), __ldg(&edge_dst[eb]),
                                 __ldg(&n2r[b]) | (te << 8), eb);
        } else {
            sMeta[r] = make_int4(0, 0, 0, 0);         // safe defaults (u=v=0)
        }
    }
    if (tid < EPB) {                                  // 111 edges per block
        int e = bid * EPB + tid;
        if (e < E_EDGES) {
            int s = __ldg(&edge_src[e]), d0 = __ldg(&edge_dst[e]), t = __ldg(&edge_type[e]);
            int p = atomicAdd(&cntA[s], 1);
            if (p < CAP) g_list[s * CAP + p] = (d0 << 8) | t;
            int q = atomicAdd(&cntA[N_NODES + d0], 1);
            if (q < CAP) g_list[(N_NODES + d0) * CAP + q] = (s << 8) | t;
        }
    }
    if (tid >= 128 && tid < 128 + CZPB) {             // 56 counter zeros
        int z = bid * CZPB + (tid - 128);
        if (z < 2 * N_NODES) cntZ[z] = 0;
    }

    // Gram (threads 0-270) and Y (threads 512-771) in parallel
    if (tid < GPB) {
        int g = bid * GPB + tid;
        if (g < NUM_REL * NUM_REL) {
            int a = g / NUM_REL, bb = g - a * NUM_REL;
            float s = 0.f;
            #pragma unroll
            for (int k = 0; k < 32; k++) s += srel[a * 33 + k] * srel[bb * 33 + k];
            g_R[a * 256 + bb] = s > 0.f ? s : 0.2f * s;
        }
    } else if (tid >= 512 && tid < 512 + YPB) {
        int g = bid * YPB + (tid - 512);
        if (g < 6 * NUM_REL * D) {
            int d = g & 31, rest = g >> 5;
            int t = rest % NUM_REL, i = rest / NUM_REL;
            float s = 0.f;
            #pragma unroll
            for (int k = 0; k < 32; k++)
                s += srel[t * 33 + k] * sWT[i * 1056 + k * 33 + d];
            g_Y[(i * 256 + t) * 32 + d] = s;
        }
    }

    // ---- h0 copy: unconditional, PRE-barrier (owner overwrites its rows later) ----
    if (tid < CPB) {
        int idx = bid * CPB + tid;
        if (idx < E_EDGES * D / 4) {
            int e = idx >> 3;
            int t = __ldg(&edge_type[e]);
            ((float4*)out)[idx] = __ldg(&((const float4*)rel_emb)[t * 8 + (idx & 7)]);
        }
    }

    // ---- distributed-flag grid barrier (148 flags, 5 polls/lane) ----
    __syncthreads();
    const unsigned target = ep0 + 1;
    if (bid == 0 && tid < 32) {
        if (tid == 0) st_rel(&g_arrive[0], target);
        for (;;) {
            int ok = 0;
            #pragma unroll
            for (int j = 0; j < 5; j++) {
                int idx = tid * 5 + j;
                ok += (idx >= GRID_BLOCKS) || (ld_acq(&g_arrive[idx]) == target);
            }
            if (__all_sync(FULL, ok == 5)) break;
        }
        if (tid == 0) st_rel(&g_epoch, target);
    } else if (tid == 0) {
        st_rel(&g_arrive[bid], target);
    }
    if (tid == 0) { while (ld_acq(&g_epoch) != target) { } }
    __syncthreads();

    // ---- phase B: two warps per row, all loads hoisted and independent ----
    const int lane = tid & 31, warp = tid >> 5;
    const int pr = warp >> 1;                         // 0..15 (rows 0..13 valid)
    const bool evenW = !(warp & 1);
    const int b = bid * RPB + pr;
    const bool rowValid = (pr < RPB) && (b < B_ROWS);
    int4 meta = rowValid ? sMeta[pr] : make_int4(0, 0, 0, 0);
    const int u = meta.x, v = meta.y, eb = meta.w;
    const int tEb = (meta.z >> 8) & 255;
    const int relbase = (meta.z & 255) * 256;
    const int off = evenW ? 0 : N_NODES;              // even: src buckets, odd: dst
    const int n1 = off + u, n2 = off + v;
    const int b1o = n1 * CAP, b2o = n2 * CAP;

    int rc1 = __ldg(&cntA[n1]);                       // 6 independent loads in flight
    int rc2 = __ldg(&cntA[n2]);
    int pk1a = __ldg(&g_list[b1o + lane]);
    int pk1b = __ldg(&g_list[b1o + lane + 32]);
    int pk2a = __ldg(&g_list[b2o + lane]);
    int pk2b = __ldg(&g_list[b2o + lane + 32]);

    float sc1a = __ldg(&g_R[relbase + (pk1a & 255)]); // 4 independent score loads
    float sc1b = __ldg(&g_R[relbase + (pk1b & 255)]);
    float sc2a = __ldg(&g_R[relbase + (pk2a & 255)]);
    float sc2b = __ldg(&g_R[relbase + (pk2b & 255)]);

    const int c1 = min(rc1, CAP), c2 = min(rc2, CAP);
    const int mE1 = evenW ? 1 : 0, mE2 = evenW ? 3 : 2;
    bool va1 = lane < c1, vb1 = lane + 32 < c1;
    bool va2 = lane < c2, vb2 = lane + 32 < c2;
    bool i1a = (pk1a >> 8) == v, i1b = (pk1b >> 8) == v;
    bool i2a = (pk2a >> 8) == u, i2b = (pk2b >> 8) == u;

    bool q1a = va1 && sc1a != 0.f && (evenW || !i1a);
    bool q1b = vb1 && sc1b != 0.f && (evenW || !i1b);
    bool q2a = va2 && sc2a != 0.f && (evenW || !i2a);
    bool q2b = vb2 && sc2b != 0.f && (evenW || !i2b);
    float ex1a = q1a ? __expf(sc1a) : 0.f;            // no max-shift: |sc| small
    float ex1b = q1b ? __expf(sc1b) : 0.f;
    float ex2a = q2a ? __expf(sc2a) : 0.f;
    float ex2b = q2b ? __expf(sc2b) : 0.f;

    float LM1 = (i1a ? ex1a : 0.f) + (i1b ? ex1b : 0.f);
    float LE1 = (!i1a ? ex1a : 0.f) + (!i1b ? ex1b : 0.f);
    float LM2 = (i2a ? ex2a : 0.f) + (i2b ? ex2b : 0.f);
    float LE2 = (!i2a ? ex2a : 0.f) + (!i2b ? ex2b : 0.f);
    #pragma unroll
    for (int o = 16; o; o >>= 1) {                    // 4 interleaved butterflies
        LM1 += __shfl_xor_sync(FULL, LM1, o);
        LE1 += __shfl_xor_sync(FULL, LE1, o);
        LM2 += __shfl_xor_sync(FULL, LM2, o);
        LE2 += __shfl_xor_sync(FULL, LE2, o);
    }
    float rM1 = LM1 > 0.f ? __fdividef(1.f, LM1) : 0.f;
    float rE1 = LE1 > 0.f ? __fdividef(1.f, LE1) : 0.f;
    float rM2 = LM2 > 0.f ? __fdividef(1.f, LM2) : 0.f;
    float rE2 = LE2 > 0.f ? __fdividef(1.f, LE2) : 0.f;
    float p1a = ex1a * (i1a ? rM1 : rE1);
    float p1b = ex1b * (i1b ? rM1 : rE1);
    float p2a = ex2a * (i2a ? rM2 : rE2);
    float p2b = ex2b * (i2b ? rM2 : rE2);
    int y1a = (((i1a ? 4 : mE1) * 256 + (pk1a & 255)) << 5);   // padded, in-bounds
    int y1b = (((i1b ? 4 : mE1) * 256 + (pk1b & 255)) << 5);
    int y2a = (((i2a ? 5 : mE2) * 256 + (pk2a & 255)) << 5);
    int y2b = (((i2b ? 5 : mE2) * 256 + (pk2b & 255)) << 5);

    float agg = 0.f;                                   // bias per non-empty mode
    if (LE1 > 0.f) agg += sB[mE1 * 32 + lane];
    if (LE2 > 0.f) agg += sB[mE2 * 32 + lane];
    if (evenW) {
        if (LM1 > 0.f) agg += sB[4 * 32 + lane];
        if (LM2 > 0.f) agg += sB[5 * 32 + lane];
    }

    // branch-free pipelined gathers (pp==0 lanes contribute exactly 0)
    int lim1 = min(c1, 32), lim2 = min(c2, 32);
    #pragma unroll 4
    for (int k = 0; k < lim1; k++) {
        float pp = __shfl_sync(FULL, p1a, k);
        int ix = __shfl_sync(FULL, y1a, k);
        agg += pp * __ldg(&g_Y[ix + lane]);
    }
    #pragma unroll 4
    for (int k = 0; k < lim2; k++) {
        float pp = __shfl_sync(FULL, p2a, k);
        int ix = __shfl_sync(FULL, y2a, k);
        agg += pp * __ldg(&g_Y[ix + lane]);
    }
    if (c1 > 32) for (int k = 0; k < c1 - 32; k++) {   // rare overflow chunks
        float pp = __shfl_sync(FULL, p1b, k);
        int ix = __shfl_sync(FULL, y1b, k);
        agg += pp * __ldg(&g_Y[ix + lane]);
    }
    if (c2 > 32) for (int k = 0; k < c2 - 32; k++) {
        float pp = __shfl_sync(FULL, p2b, k);
        int ix = __shfl_sync(FULL, y2b, k);
        agg += pp * __ldg(&g_Y[ix + lane]);
    }

    if (!evenW && rowValid) s_agg[pr * 32 + lane] = agg;
    __syncthreads();
    if (evenW && rowValid) {
        float tot = agg + s_agg[pr * 32 + lane];
        float hN = tot > 0.f ? tot : 0.f;
        // overwrites this row's pre-barrier copy; ordered by the grid barrier
        out[(eb << 5) | lane] = srel[tEb * 33 + lane] + hN;
    }
}

// ---------------- launcher: ONE kernel, dynamic smem ----------------
extern "C" void kernel_launch(void* const* d_in, const int* in_sizes, int n_in,
                              void* d_out, int out_size) {
    const int*   edge_src  = (const int*)d_in[0];
    const int*   edge_dst  = (const int*)d_in[1];
    const int*   edge_type = (const int*)d_in[2];
    const int*   nbr       = (const int*)d_in[3];
    const int*   n2r       = (const int*)d_in[4];
    const float* rel_emb   = (const float*)d_in[5];
    const float* W1        = (const float*)d_in[6];
    const float* b1        = (const float*)d_in[7];
    float* out = (float*)d_out;

    const int SMEM_BYTES = 13640 * 4 + 16 * 16;   // 54816
    cudaFuncSetAttribute(k_fused, cudaFuncAttributeMaxDynamicSharedMemorySize, SMEM_BYTES);
    k_fused<<<GRID_BLOCKS, BLOCK_THREADS, SMEM_BYTES>>>(
        edge_src, edge_dst, edge_type, nbr, n2r, rel_emb, W1, b1, out);
}

// round 14
// speedup vs baseline: 1.1272x; 1.1272x over previous
#include <cuda_runtime.h>

#define N_NODES 4096
#define NUM_REL 200
#define D 32
#define E_EDGES 16384
#define B_ROWS 2048
#define CAP 64
#define FULL 0xffffffffu
#define GRID_BLOCKS 128
#define BLOCK_THREADS 1024

// ---------------- persistent scratch (no allocation) ----------------
__device__ int      g_cnt[2][2 * N_NODES];       // ping-pong by epoch parity
__device__ unsigned g_bm[2][E_EDGES / 32];       // neighbor-row bitmap, ping-pong
__device__ int      g_list[2 * N_NODES * CAP];   // packed (other<<8)|type
__device__ float    g_Y[6 * 256 * 32];           // padded type dim: any ty<=255 in-bounds
__device__ float    g_R[NUM_REL * 256];          // padded rows: any ty<=255 in-bounds
__device__ unsigned g_arrive[GRID_BLOCKS];       // per-block arrival flags
__device__ unsigned g_epoch = 0;

__device__ __forceinline__ unsigned ld_acq(const unsigned* p) {
    unsigned v;
    asm volatile("ld.acquire.gpu.u32 %0, [%1];" : "=r"(v) : "l"(p) : "memory");
    return v;
}
__device__ __forceinline__ void st_rel(unsigned* p, unsigned v) {
    asm volatile("st.release.gpu.u32 [%0], %1;" :: "l"(p), "r"(v) : "memory");
}

__global__ void __launch_bounds__(BLOCK_THREADS, 1)
k_fused(const int* __restrict__ edge_src, const int* __restrict__ edge_dst,
        const int* __restrict__ edge_type, const int* __restrict__ nbr,
        const int* __restrict__ n2r, const float* __restrict__ rel_emb,
        const float* __restrict__ W1, const float* __restrict__ b1,
        float* __restrict__ out) {
    extern __shared__ float smem[];
    float* srel  = smem;                   // [200*33] padded
    float* sWT   = smem + 6600;            // [6*1056] sWT[i*1056+k*33+d]=W1[i][d][k]
    float* sB    = smem + 12936;           // [192]
    float* s_agg = smem + 13128;           // [16*32]
    int4*  sMeta = (int4*)(smem + 13640);  // [16] (u, v, relb|te<<8, eb)
    __shared__ unsigned s_ep;

    const int tid = threadIdx.x, bid = blockIdx.x;

    // epoch: ONE acquire load per block, broadcast through smem
    if (tid == 0) s_ep = ld_acq(&g_epoch);

    // ---- vectorized smem staging (independent of epoch) ----
    for (int idx = tid; idx < 1600; idx += BLOCK_THREADS) {   // rel_emb: 1600 float4
        float4 v = __ldg(&((const float4*)rel_emb)[idx]);
        int base = idx << 2, t = base >> 5, rem = base & 31;
        float* dst = &srel[t * 33 + rem];
        dst[0] = v.x; dst[1] = v.y; dst[2] = v.z; dst[3] = v.w;
    }
    for (int idx = tid; idx < 1536; idx += BLOCK_THREADS) {   // W1: 1536 float4
        float4 v = __ldg(&((const float4*)W1)[idx]);
        int base = idx << 2;
        int i = base >> 10, r = base & 1023, d = r >> 5, k0 = r & 31;
        float* dst = &sWT[i * 1056 + k0 * 33 + d];            // stride 33 per k
        dst[0] = v.x; dst[33] = v.y; dst[66] = v.z; dst[99] = v.w;
    }
    if (tid >= 832 && tid < 832 + 192) sB[tid - 832] = __ldg(&b1[tid - 832]);
    __syncthreads();                         // publishes s_ep AND srel/sWT

    const unsigned ep0 = s_ep;
    int*      cntA = g_cnt[ep0 & 1];
    int*      cntZ = g_cnt[(ep0 & 1) ^ 1];
    unsigned* bmA  = g_bm[ep0 & 1];
    unsigned* bmZ  = g_bm[(ep0 & 1) ^ 1];

    // ---- balanced phase A (contiguous per-block slices) ----
    if (tid >= 896 && tid < 912) {                    // this block's 16 rows
        int r = tid - 896;
        int b = bid * 16 + r;
        int eb = __ldg(&nbr[b]);
        int te = __ldg(&edge_type[eb]);
        sMeta[r] = make_int4(__ldg(&edge_src[eb]), __ldg(&edge_dst[eb]),
                             __ldg(&n2r[b]) | (te << 8), eb);
        atomicOr(&bmA[eb >> 5], 1u << (eb & 31));     // mark neighbor row
    }
    if (tid < 128) {                                  // 128 edges per block
        int e = bid * 128 + tid;
        int s = __ldg(&edge_src[e]), d0 = __ldg(&edge_dst[e]), t = __ldg(&edge_type[e]);
        int p = atomicAdd(&cntA[s], 1);
        if (p < CAP) g_list[s * CAP + p] = (d0 << 8) | t;
        int q = atomicAdd(&cntA[N_NODES + d0], 1);
        if (q < CAP) g_list[(N_NODES + d0) * CAP + q] = (s << 8) | t;
    }
    if (tid >= 128 && tid < 192) cntZ[bid * 64 + (tid - 128)] = 0;
    if (tid >= 192 && tid < 196) bmZ[bid * 4 + (tid - 192)] = 0;

    // Gram (threads 0-312) and Y (threads 512-811) in parallel
    if (tid < 313) {
        int g = bid * 313 + tid;
        if (g < NUM_REL * NUM_REL) {
            int a = g / NUM_REL, bb = g - a * NUM_REL;
            float s = 0.f;
            #pragma unroll
            for (int k = 0; k < 32; k++) s += srel[a * 33 + k] * srel[bb * 33 + k];
            g_R[a * 256 + bb] = s > 0.f ? s : 0.2f * s;
        }
    } else if (tid >= 512 && tid < 812) {
        int g = bid * 300 + (tid - 512);              // 128*300 = 38400 exactly
        int d = g & 31, rest = g >> 5;
        int t = rest % NUM_REL, i = rest / NUM_REL;
        float s = 0.f;
        #pragma unroll
        for (int k = 0; k < 32; k++)
            s += srel[t * 33 + k] * sWT[i * 1056 + k * 33 + d];
        g_Y[(i * 256 + t) * 32 + d] = s;
    }

    // ---- distributed-flag grid barrier (release path is nearly store-free) ----
    __syncthreads();
    const unsigned target = ep0 + 1;
    if (bid == 0 && tid < 32) {
        if (tid == 0) st_rel(&g_arrive[0], target);
        for (;;) {
            bool mine = ld_acq(&g_arrive[tid * 4 + 0]) == target &&
                        ld_acq(&g_arrive[tid * 4 + 1]) == target &&
                        ld_acq(&g_arrive[tid * 4 + 2]) == target &&
                        ld_acq(&g_arrive[tid * 4 + 3]) == target;
            if (__all_sync(FULL, mine)) break;
        }
        if (tid == 0) st_rel(&g_epoch, target);
    } else if (tid == 0) {
        st_rel(&g_arrive[bid], target);
    }
    if (tid == 0) { while (ld_acq(&g_epoch) != target) { } }
    __syncthreads();

    // ---- phase B: hoisted independent loads ----
    const int lane = tid & 31, warp = tid >> 5;
    const int pr = warp >> 1;
    const bool evenW = !(warp & 1);
    int4 meta = sMeta[pr];
    const int u = meta.x, v = meta.y, eb = meta.w;
    const int tEb = (meta.z >> 8) & 255;
    const int relbase = (meta.z & 255) * 256;
    const int off = evenW ? 0 : N_NODES;              // even: src buckets, odd: dst
    const int n1 = off + u, n2 = off + v;
    const int b1o = n1 * CAP, b2o = n2 * CAP;

    int rc1 = __ldg(&cntA[n1]);                       // 6 independent loads in flight
    int rc2 = __ldg(&cntA[n2]);
    int pk1a = __ldg(&g_list[b1o + lane]);
    int pk1b = __ldg(&g_list[b1o + lane + 32]);
    int pk2a = __ldg(&g_list[b2o + lane]);
    int pk2b = __ldg(&g_list[b2o + lane + 32]);

    // ---- h0 copy for NON-neighbor rows: post-barrier, disjoint from final writes,
    //      overlaps phase B's dependent-load latency ----
    {
        int idx = bid * BLOCK_THREADS + tid;          // 131072 = E*8 float4s
        int e = idx >> 3;
        unsigned bits = __ldg(&bmA[e >> 5]);
        if (!((bits >> (e & 31)) & 1)) {
            int t = __ldg(&edge_type[e]);
            ((float4*)out)[idx] = __ldg(&((const float4*)rel_emb)[t * 8 + (idx & 7)]);
        }
    }

    float sc1a = __ldg(&g_R[relbase + (pk1a & 255)]); // 4 independent score loads
    float sc1b = __ldg(&g_R[relbase + (pk1b & 255)]);
    float sc2a = __ldg(&g_R[relbase + (pk2a & 255)]);
    float sc2b = __ldg(&g_R[relbase + (pk2b & 255)]);

    const int c1 = min(rc1, CAP), c2 = min(rc2, CAP);
    const int mE1 = evenW ? 1 : 0, mE2 = evenW ? 3 : 2;
    bool va1 = lane < c1, vb1 = lane + 32 < c1;
    bool va2 = lane < c2, vb2 = lane + 32 < c2;
    bool i1a = (pk1a >> 8) == v, i1b = (pk1b >> 8) == v;
    bool i2a = (pk2a >> 8) == u, i2b = (pk2b >> 8) == u;

    bool q1a = va1 && sc1a != 0.f && (evenW || !i1a);
    bool q1b = vb1 && sc1b != 0.f && (evenW || !i1b);
    bool q2a = va2 && sc2a != 0.f && (evenW || !i2a);
    bool q2b = vb2 && sc2b != 0.f && (evenW || !i2b);
    float ex1a = q1a ? __expf(sc1a) : 0.f;            // no max-shift: |sc| small
    float ex1b = q1b ? __expf(sc1b) : 0.f;
    float ex2a = q2a ? __expf(sc2a) : 0.f;
    float ex2b = q2b ? __expf(sc2b) : 0.f;

    float LM1 = (i1a ? ex1a : 0.f) + (i1b ? ex1b : 0.f);
    float LE1 = (!i1a ? ex1a : 0.f) + (!i1b ? ex1b : 0.f);
    float LM2 = (i2a ? ex2a : 0.f) + (i2b ? ex2b : 0.f);
    float LE2 = (!i2a ? ex2a : 0.f) + (!i2b ? ex2b : 0.f);
    #pragma unroll
    for (int o = 16; o; o >>= 1) {                    // 4 interleaved butterflies
        LM1 += __shfl_xor_sync(FULL, LM1, o);
        LE1 += __shfl_xor_sync(FULL, LE1, o);
        LM2 += __shfl_xor_sync(FULL, LM2, o);
        LE2 += __shfl_xor_sync(FULL, LE2, o);
    }
    float rM1 = LM1 > 0.f ? __fdividef(1.f, LM1) : 0.f;
    float rE1 = LE1 > 0.f ? __fdividef(1.f, LE1) : 0.f;
    float rM2 = LM2 > 0.f ? __fdividef(1.f, LM2) : 0.f;
    float rE2 = LE2 > 0.f ? __fdividef(1.f, LE2) : 0.f;
    float p1a = ex1a * (i1a ? rM1 : rE1);
    float p1b = ex1b * (i1b ? rM1 : rE1);
    float p2a = ex2a * (i2a ? rM2 : rE2);
    float p2b = ex2b * (i2b ? rM2 : rE2);
    int y1a = (((i1a ? 4 : mE1) * 256 + (pk1a & 255)) << 5);   // padded, in-bounds
    int y1b = (((i1b ? 4 : mE1) * 256 + (pk1b & 255)) << 5);
    int y2a = (((i2a ? 5 : mE2) * 256 + (pk2a & 255)) << 5);
    int y2b = (((i2b ? 5 : mE2) * 256 + (pk2b & 255)) << 5);

    float agg = 0.f;                                   // bias per non-empty mode
    if (LE1 > 0.f) agg += sB[mE1 * 32 + lane];
    if (LE2 > 0.f) agg += sB[mE2 * 32 + lane];
    if (evenW) {
        if (LM1 > 0.f) agg += sB[4 * 32 + lane];
        if (LM2 > 0.f) agg += sB[5 * 32 + lane];
    }

    // branch-free pipelined gathers (pp==0 lanes contribute exactly 0)
    int lim1 = min(c1, 32), lim2 = min(c2, 32);
    #pragma unroll 4
    for (int k = 0; k < lim1; k++) {
        float pp = __shfl_sync(FULL, p1a, k);
        int ix = __shfl_sync(FULL, y1a, k);
        agg += pp * __ldg(&g_Y[ix + lane]);
    }
    #pragma unroll 4
    for (int k = 0; k < lim2; k++) {
        float pp = __shfl_sync(FULL, p2a, k);
        int ix = __shfl_sync(FULL, y2a, k);
        agg += pp * __ldg(&g_Y[ix + lane]);
    }
    if (c1 > 32) for (int k = 0; k < c1 - 32; k++) {   // rare overflow chunks
        float pp = __shfl_sync(FULL, p1b, k);
        int ix = __shfl_sync(FULL, y1b, k);
        agg += pp * __ldg(&g_Y[ix + lane]);
    }
    if (c2 > 32) for (int k = 0; k < c2 - 32; k++) {
        float pp = __shfl_sync(FULL, p2b, k);
        int ix = __shfl_sync(FULL, y2b, k);
        agg += pp * __ldg(&g_Y[ix + lane]);
    }

    if (!evenW) s_agg[pr * 32 + lane] = agg;
    __syncthreads();
    if (evenW) {
        float tot = agg + s_agg[pr * 32 + lane];
        float hN = tot > 0.f ? tot : 0.f;
        // neighbor rows skipped by the copy -> this is the only writer of this row
        out[(eb << 5) | lane] = srel[tEb * 33 + lane] + hN;
    }
}

// ---------------- launcher: ONE kernel, dynamic smem ----------------
extern "C" void kernel_launch(void* const* d_in, const int* in_sizes, int n_in,
                              void* d_out, int out_size) {
    const int*   edge_src  = (const int*)d_in[0];
    const int*   edge_dst  = (const int*)d_in[1];
    const int*   edge_type = (const int*)d_in[2];
    const int*   nbr       = (const int*)d_in[3];
    const int*   n2r       = (const int*)d_in[4];
    const float* rel_emb   = (const float*)d_in[5];
    const float* W1        = (const float*)d_in[6];
    const float* b1        = (const float*)d_in[7];
    float* out = (float*)d_out;

    const int SMEM_BYTES = 13640 * 4 + 16 * 16;   // 54816
    cudaFuncSetAttribute(k_fused, cudaFuncAttributeMaxDynamicSharedMemorySize, SMEM_BYTES);
    k_fused<<<GRID_BLOCKS, BLOCK_THREADS, SMEM_BYTES>>>(
        edge_src, edge_dst, edge_type, nbr, n2r, rel_emb, W1, b1, out);
}